// round 15
// baseline (speedup 1.0000x reference)
#include <cuda_runtime.h>
#include <cuda_fp16.h>
#include <math.h>

#define B   16
#define S   1024
#define NF  5
#define D   64
#define H   8
#define HD  8
#define NL  2
#define FF  128
#define NQ  8
#define QL  3
#define BS  (B*S)
#define CK2  512
#define VPAD2 520

typedef unsigned long long ull;
typedef unsigned int uint;

// ---------------- device scratch ----------------
__device__ float g_h  [BS*D];
__device__ uint  g_q16[BS*32];                 // half2-packed q
__device__ uint  g_k16[BS*32];                 // half2-packed k, pre-scaled
__device__ uint  g_v16[BS*32];                 // half2-packed v
__device__ float g_pe [S*D];
__device__ uint  g_parth[(size_t)2*128*S*6];   // fp16 partials (4 half2 + lsum f32 + pad)
__device__ float g_poolp[B*4*D];
// prepacked half2 weights (B-fragment layout)
__device__ uint g_pWq[NL*32*68];
__device__ uint g_pWk[NL*32*68];
__device__ uint g_pWv[NL*32*68];
__device__ uint g_pWo[NL*32*68];
__device__ uint g_pW1[NL*32*132];
__device__ uint g_pW2[NL*64*68];

// ---------------- mma / f16 / async helpers ----------------
__device__ __forceinline__ void mma16n8k8_f16(uint& d0, uint& d1, uint a0, uint a1, uint b0) {
    asm volatile("mma.sync.aligned.m16n8k8.row.col.f16.f16.f16.f16 "
        "{%0,%1}, {%2,%3}, {%4}, {%5,%6};"
        : "=r"(d0), "=r"(d1)
        : "r"(a0), "r"(a1), "r"(b0), "r"(0u), "r"(0u));
}
__device__ __forceinline__ void mma16n8k16(float* d,
                                           uint a0, uint a1, uint a2, uint a3,
                                           uint b0, uint b1) {
    asm volatile("mma.sync.aligned.m16n8k16.row.col.f32.f16.f16.f32 "
        "{%0,%1,%2,%3}, {%4,%5,%6,%7}, {%8,%9}, {%0,%1,%2,%3};"
        : "+f"(d[0]), "+f"(d[1]), "+f"(d[2]), "+f"(d[3])
        : "r"(a0), "r"(a1), "r"(a2), "r"(a3), "r"(b0), "r"(b1));
}
__device__ __forceinline__ uint cvt_f16x2(float hi, float lo) {
    uint r; asm("cvt.rn.f16x2.f32 %0, %1, %2;" : "=r"(r) : "f"(hi), "f"(lo)); return r;
}
__device__ __forceinline__ uint hex2x2(uint x) {
    uint r; asm("ex2.approx.f16x2 %0, %1;" : "=r"(r) : "r"(x)); return r;
}
__device__ __forceinline__ void cpasync16(uint smem_addr, const void* gptr) {
    asm volatile("cp.async.cg.shared.global [%0], [%1], 16;" :: "r"(smem_addr), "l"(gptr));
}
#define CP_COMMIT()  asm volatile("cp.async.commit_group;" ::: "memory")
#define CP_WAIT(n)   asm volatile("cp.async.wait_group %0;" :: "n"(n) : "memory")
__device__ __forceinline__ uint smem_u32p(const void* p) {
    return (uint)__cvta_generic_to_shared(p);
}

// ---------------- complex helpers ----------------
__device__ __forceinline__ float2 cmul(float2 a, float2 b) {
    return make_float2(a.x*b.x - a.y*b.y, a.x*b.y + a.y*b.x);
}
__device__ __forceinline__ float2 cmulcj(float2 a, float2 b) {
    return make_float2(a.x*b.x + a.y*b.y, a.x*b.y - a.y*b.x);
}
__device__ __forceinline__ float2 cadd(float2 a, float2 b) {
    return make_float2(a.x + b.x, a.y + b.y);
}

// ---------------- 0) init: pe table + weight prepack ----------------
__global__ void k_init(const float* __restrict__ Wq, const float* __restrict__ Wk,
                       const float* __restrict__ Wv, const float* __restrict__ Wo,
                       const float* __restrict__ Wf1, const float* __restrict__ Wf2) {
    int bidx = blockIdx.x;
    int tid = threadIdx.x;
    if (bidx < 128) {
        int idx = bidx * 256 + tid;
        int s = idx >> 5, p = idx & 31;
        float div = __expf(-0.14391156831212787f * (float)(2*p));
        float sn, cs;
        sincosf((float)s * div, &sn, &cs);
        g_pe[s*64 + 2*p]     = sn;
        g_pe[s*64 + 2*p + 1] = cs;
    } else {
        int idx = (bidx - 128) * 256 + tid;    // < NL*16384
        int l = idx / 16384;
        int r = idx % 16384;
        if (r < 8192) {
            int m = r >> 11;
            int q = r & 2047;
            int ip = q >> 6, n = q & 63;
            const float* W = (m == 0) ? (Wq + l*4096) : (m == 1) ? (Wk + l*4096)
                           : (m == 2) ? (Wv + l*4096) : (Wo + l*4096);
            uint* dst = (m == 0) ? g_pWq : (m == 1) ? g_pWk : (m == 2) ? g_pWv : g_pWo;
            dst[l*2176 + ip*68 + n] = cvt_f16x2(W[(2*ip+1)*64 + n], W[(2*ip)*64 + n]);
        } else if (r < 12288) {
            int q = r - 8192;
            int ip = q >> 7, n = q & 127;
            const float* W = Wf1 + l*8192;
            g_pW1[l*4224 + ip*132 + n] = cvt_f16x2(W[(2*ip+1)*128 + n], W[(2*ip)*128 + n]);
        } else {
            int q = r - 12288;
            int ip = q >> 6, n = q & 63;
            const float* W = Wf2 + l*8192;
            g_pW2[l*4352 + ip*68 + n] = cvt_f16x2(W[(2*ip+1)*64 + n], W[(2*ip)*64 + n]);
        }
    }
}

// ======== MMA GEMM common fragment loaders ========
__device__ __forceinline__ void load_afrag64(uint (&a)[4][4], const uint* sA, int rbase, int gid, int tig) {
    const uint* r0 = sA + (rbase + gid)*36;
    const uint* r1 = sA + (rbase + gid + 8)*36;
#pragma unroll
    for (int kk = 0; kk < 4; kk++) {
        a[kk][0] = r0[kk*8 + tig];
        a[kk][1] = r1[kk*8 + tig];
        a[kk][2] = r0[kk*8 + 4 + tig];
        a[kk][3] = r1[kk*8 + 4 + tig];
    }
}

// ---------------- 1) QKV projection: cp.async weights, fp16 outputs ----------------
__global__ void __launch_bounds__(64) k_qkv_mma(
        const float* __restrict__ bq, const float* __restrict__ bk,
        const float* __restrict__ bv,
        const float* __restrict__ x,  const float* __restrict__ Wemb,
        const float* __restrict__ bemb, int l) {
    __shared__ uint  sA [32*36];
    __shared__ uint  sW [2176];
    __shared__ float sX [32*NF];
    int tid = threadIdx.x;
    int row0 = blockIdx.x * 32;
    int m = blockIdx.y;
    const uint* pW    = ((m == 0) ? g_pWq : (m == 1) ? g_pWk : g_pWv) + l*2176;
    const float* bias = ((m == 0) ? bq : (m == 1) ? bk : bv) + l*D;
    uint* out         = (m == 0) ? g_q16 : (m == 1) ? g_k16 : g_v16;
    const float pre   = 0.35355339059327373f * 1.4426950408889634f;
    const float oscale = (m == 1) ? pre : 1.0f;   // pre-scale K

    {
        uint sw = smem_u32p(sW);
        for (int i = tid; i < 544; i += 64)
            cpasync16(sw + i*16, pW + i*4);
        CP_COMMIT();
    }

    if (l == 0) {
        for (int idx = tid; idx < 32*NF; idx += 64)
            sX[idx] = x[(size_t)(row0 + idx/NF)*NF + idx%NF];
        __syncthreads();
        for (int idx = tid; idx < 1024; idx += 64) {
            int r = idx >> 5, c2 = idx & 31;
            int row = row0 + r;
            int s = row & (S-1);
            int c = c2*2;
            float v0 = bemb[c]   + g_pe[s*64 + c];
            float v1 = bemb[c+1] + g_pe[s*64 + c + 1];
            const float* xr = sX + r*NF;
#pragma unroll
            for (int f = 0; f < NF; f++) {
                v0 += xr[f] * Wemb[f*D + c];
                v1 += xr[f] * Wemb[f*D + c + 1];
            }
            sA[r*36 + c2] = cvt_f16x2(v1, v0);
            if (m == 0) *(float2*)(g_h + (size_t)row*D + c) = make_float2(v0, v1);
        }
    } else {
        for (int idx = tid; idx < 1024; idx += 64) {
            int r = idx >> 5, c2 = idx & 31;
            float2 v = *(const float2*)(g_h + (size_t)(row0 + r)*D + c2*2);
            sA[r*36 + c2] = cvt_f16x2(v.y, v.x);
        }
    }
    CP_WAIT(0);
    __syncthreads();

    int warp = tid >> 5, lane = tid & 31;
    int gid = lane >> 2, tig = lane & 3;
    uint a[4][4];
    load_afrag64(a, sA, warp*16, gid, tig);

#pragma unroll
    for (int t = 0; t < 8; t++) {
        float acc[4] = {0,0,0,0};
#pragma unroll
        for (int kk = 0; kk < 4; kk++) {
            uint b0 = sW[(kk*8 + tig)*68 + t*8 + gid];
            uint b1 = sW[(kk*8 + 4 + tig)*68 + t*8 + gid];
            mma16n8k16(acc, a[kk][0], a[kk][1], a[kk][2], a[kk][3], b0, b1);
        }
        float2 bv2 = *(const float2*)(bias + t*8 + tig*2);
        int r = row0 + warp*16 + gid;
        out[(size_t)r*32 + t*4 + tig] =
            cvt_f16x2((acc[1] + bv2.y) * oscale, (acc[0] + bv2.x) * oscale);
        out[(size_t)(r + 8)*32 + t*4 + tig] =
            cvt_f16x2((acc[3] + bv2.y) * oscale, (acc[2] + bv2.x) * oscale);
    }
}

// ---------------- 2) split-K attention: fp16 inputs, E/O chains, fp16 partials ----------------
__global__ void __launch_bounds__(128) k_attn_mma() {
    __shared__ uint   sK [CK2*4];     // half2 units, [key][4]
    __shared__ __half sVT[8*VPAD2];
    int tid = threadIdx.x;
    int bh  = blockIdx.y;
    int b   = bh >> 3, hh = bh & 7;
    int qt  = blockIdx.x >> 1;
    int ck  = blockIdx.x & 1;
    int k0  = ck * CK2;
    const uint*   kbase  = g_k16 + (size_t)(b*S + k0)*32 + hh*4;
    const __half* vbaseh = (const __half*)g_v16 + ((size_t)(b*S + k0)*32 + hh*4)*2;
    // K: packed copy (no math)
    for (int i = tid; i < CK2*4; i += 128) {
        int key = i >> 2, u = i & 3;
        sK[i] = kbase[(size_t)key*32 + u];
    }
    // V: transposed fill
    for (int i = tid; i < CK2*8; i += 128) {
        int key = i >> 3, d = i & 7;
        sVT[d*VPAD2 + key] = vbaseh[(size_t)key*64 + d];
    }
    __syncthreads();

    int warp = tid >> 5, lane = tid & 31;
    int gid  = lane >> 2, tig = lane & 3;
    int q0   = qt * 128 + warp * 32;

    uint qa[2][2];
#pragma unroll
    for (int t2 = 0; t2 < 2; t2++) {
#pragma unroll
        for (int hf = 0; hf < 2; hf++) {
            int qrow = q0 + t2*16 + gid + hf*8;
            qa[t2][hf] = g_q16[(size_t)(b*S + qrow)*32 + hh*4 + tig];
        }
    }

    float acc0E[4] = {0,0,0,0}, acc0O[4] = {0,0,0,0};
    float acc1E[4] = {0,0,0,0}, acc1O[4] = {0,0,0,0};
    float lac0E[4] = {0,0,0,0}, lac0O[4] = {0,0,0,0};
    float lac1E[4] = {0,0,0,0}, lac1O[4] = {0,0,0,0};
    const uint ones2 = 0x3C003C00u;
    const uint*   kptr = sK + gid*4 + tig;        // [key*4] stride per 8 keys: 32
    const __half* vptr = sVT + gid*VPAD2 + tig*2;

    for (int j0 = 0; j0 < CK2; j0 += 32) {
        uint kb0 = kptr[j0*4];
        uint kb1 = kptr[j0*4 + 32];
        uint kb2 = kptr[j0*4 + 64];
        uint kb3 = kptr[j0*4 + 96];
        uint vb0 = *(const uint*)(vptr + j0);
        uint vb1 = *(const uint*)(vptr + j0 + 8);
        uint vb2 = *(const uint*)(vptr + j0 + 16);
        uint vb3 = *(const uint*)(vptr + j0 + 24);
        {
            uint s01a, s23a, s01b, s23b;
            mma16n8k8_f16(s01a, s23a, qa[0][0], qa[0][1], kb0);
            mma16n8k8_f16(s01b, s23b, qa[0][0], qa[0][1], kb1);
            uint p0 = hex2x2(s01a), p1 = hex2x2(s23a);
            uint p2 = hex2x2(s01b), p3 = hex2x2(s23b);
            mma16n8k16(acc0E, p0, p1, p2, p3, vb0, vb1);
            mma16n8k16(lac0E, p0, p1, p2, p3, ones2, ones2);
        }
        {
            uint s01a, s23a, s01b, s23b;
            mma16n8k8_f16(s01a, s23a, qa[1][0], qa[1][1], kb0);
            mma16n8k8_f16(s01b, s23b, qa[1][0], qa[1][1], kb1);
            uint p0 = hex2x2(s01a), p1 = hex2x2(s23a);
            uint p2 = hex2x2(s01b), p3 = hex2x2(s23b);
            mma16n8k16(acc1E, p0, p1, p2, p3, vb0, vb1);
            mma16n8k16(lac1E, p0, p1, p2, p3, ones2, ones2);
        }
        {
            uint s01a, s23a, s01b, s23b;
            mma16n8k8_f16(s01a, s23a, qa[0][0], qa[0][1], kb2);
            mma16n8k8_f16(s01b, s23b, qa[0][0], qa[0][1], kb3);
            uint p0 = hex2x2(s01a), p1 = hex2x2(s23a);
            uint p2 = hex2x2(s01b), p3 = hex2x2(s23b);
            mma16n8k16(acc0O, p0, p1, p2, p3, vb2, vb3);
            mma16n8k16(lac0O, p0, p1, p2, p3, ones2, ones2);
        }
        {
            uint s01a, s23a, s01b, s23b;
            mma16n8k8_f16(s01a, s23a, qa[1][0], qa[1][1], kb2);
            mma16n8k8_f16(s01b, s23b, qa[1][0], qa[1][1], kb3);
            uint p0 = hex2x2(s01a), p1 = hex2x2(s23a);
            uint p2 = hex2x2(s01b), p3 = hex2x2(s23b);
            mma16n8k16(acc1O, p0, p1, p2, p3, vb2, vb3);
            mma16n8k16(lac1O, p0, p1, p2, p3, ones2, ones2);
        }
    }

    // merge + pack fp16; layout [ck][bh][q][6 uints]
    size_t base = ((size_t)ck*128 + bh)*S;
    {
        uint* pp = g_parth + (base + q0 + gid)*6;
        pp[tig] = cvt_f16x2(acc0E[1] + acc0O[1], acc0E[0] + acc0O[0]);
        if (tig == 0) pp[4] = __float_as_uint(lac0E[0] + lac0O[0]);
        pp = g_parth + (base + q0 + gid + 8)*6;
        pp[tig] = cvt_f16x2(acc0E[3] + acc0O[3], acc0E[2] + acc0O[2]);
        if (tig == 0) pp[4] = __float_as_uint(lac0E[2] + lac0O[2]);
        pp = g_parth + (base + q0 + 16 + gid)*6;
        pp[tig] = cvt_f16x2(acc1E[1] + acc1O[1], acc1E[0] + acc1O[0]);
        if (tig == 0) pp[4] = __float_as_uint(lac1E[0] + lac1O[0]);
        pp = g_parth + (base + q0 + 24 + gid)*6;
        pp[tig] = cvt_f16x2(acc1E[3] + acc1O[3], acc1E[2] + acc1O[2]);
        if (tig == 0) pp[4] = __float_as_uint(lac1E[2] + lac1O[2]);
    }
}

// ---------------- 3) FUSED block: cp.async-staged weights, fp16 partial combine ----------------
__global__ void __launch_bounds__(64) k_block_mma(
        const float* __restrict__ bo,
        const float* __restrict__ g1, const float* __restrict__ b1,
        const float* __restrict__ bf1, const float* __restrict__ bf2,
        const float* __restrict__ g2, const float* __restrict__ b2, int l) {
    __shared__ uint sA [32*36];
    __shared__ uint sWo[2176];
    __shared__ uint sW1[4224];
    __shared__ uint sW2[4352];
    int tid = threadIdx.x;
    int row0 = blockIdx.x * 32;

    {
        const uint* pWo = g_pWo + l*2176;
        const uint* pW1 = g_pW1 + l*4224;
        const uint* pW2 = g_pW2 + l*4352;
        uint so = smem_u32p(sWo), s1 = smem_u32p(sW1), s2 = smem_u32p(sW2);
        for (int i = tid; i < 544; i += 64)  cpasync16(so + i*16, pWo + i*4);
        CP_COMMIT();
        for (int i = tid; i < 1056; i += 64) cpasync16(s1 + i*16, pW1 + i*4);
        CP_COMMIT();
        for (int i = tid; i < 1088; i += 64) cpasync16(s2 + i*16, pW2 + i*4);
        CP_COMMIT();
    }

    for (int idx = tid; idx < 1024; idx += 64) {
        int r = idx >> 5, c2 = idx & 31;
        int grow = row0 + r;
        int q  = grow & (S-1);
        int bb = grow >> 10;
        int hh = c2 >> 2;
        int bh = bb*8 + hh;
        int pi = c2 & 3;
        const uint* p0 = g_parth + ((size_t)(0*128 + bh)*S + q)*6;
        const uint* p1 = g_parth + ((size_t)(1*128 + bh)*S + q)*6;
        float2 a0 = __half22float2(*(const __half2*)&p0[pi]);
        float2 a1 = __half22float2(*(const __half2*)&p1[pi]);
        float inv = 1.0f / (__uint_as_float(p0[4]) + __uint_as_float(p1[4]));
        sA[r*36 + c2] = cvt_f16x2((a0.y + a1.y) * inv, (a0.x + a1.x) * inv);
    }
    CP_WAIT(2);
    __syncthreads();

    int warp = tid >> 5, lane = tid & 31;
    int gid = lane >> 2, tig = lane & 3;
    int rA = row0 + warp*16 + gid;
    int rB = rA + 8;

    uint a[4][4];
    load_afrag64(a, sA, warp*16, gid, tig);
    float acc[8][4];
#pragma unroll
    for (int t = 0; t < 8; t++) {
        acc[t][0]=0; acc[t][1]=0; acc[t][2]=0; acc[t][3]=0;
#pragma unroll
        for (int kk = 0; kk < 4; kk++) {
            uint b0 = sWo[(kk*8 + tig)*68 + t*8 + gid];
            uint b1 = sWo[(kk*8 + 4 + tig)*68 + t*8 + gid];
            mma16n8k16(acc[t], a[kk][0], a[kk][1], a[kk][2], a[kk][3], b0, b1);
        }
    }
    float vA[16], vB[16];
    {
        float sumA=0, sqA=0, sumB=0, sqB=0;
#pragma unroll
        for (int t = 0; t < 8; t++) {
            float2 bo2 = *(const float2*)(bo + l*D + t*8 + tig*2);
            float2 hA = *(const float2*)(g_h + (size_t)rA*D + t*8 + tig*2);
            float2 hB = *(const float2*)(g_h + (size_t)rB*D + t*8 + tig*2);
            float a0 = acc[t][0] + bo2.x + hA.x;
            float a1 = acc[t][1] + bo2.y + hA.y;
            float b0 = acc[t][2] + bo2.x + hB.x;
            float b1 = acc[t][3] + bo2.y + hB.y;
            vA[t*2]=a0; vA[t*2+1]=a1; vB[t*2]=b0; vB[t*2+1]=b1;
            sumA += a0+a1; sqA += a0*a0+a1*a1;
            sumB += b0+b1; sqB += b0*b0+b1*b1;
        }
#pragma unroll
        for (int o = 1; o < 4; o <<= 1) {
            sumA += __shfl_xor_sync(0xffffffffu, sumA, o);
            sqA  += __shfl_xor_sync(0xffffffffu, sqA,  o);
            sumB += __shfl_xor_sync(0xffffffffu, sumB, o);
            sqB  += __shfl_xor_sync(0xffffffffu, sqB,  o);
        }
        float mA = sumA*(1.f/64.f), vrA = sqA*(1.f/64.f) - mA*mA;
        float mB = sumB*(1.f/64.f), vrB = sqB*(1.f/64.f) - mB*mB;
        float rsA = rsqrtf(vrA + 1e-5f), rsB = rsqrtf(vrB + 1e-5f);
#pragma unroll
        for (int t = 0; t < 8; t++) {
            float2 gg = *(const float2*)(g1 + l*D + t*8 + tig*2);
            float2 bb = *(const float2*)(b1 + l*D + t*8 + tig*2);
            vA[t*2]   = (vA[t*2]  -mA)*rsA*gg.x + bb.x;
            vA[t*2+1] = (vA[t*2+1]-mA)*rsA*gg.y + bb.y;
            vB[t*2]   = (vB[t*2]  -mB)*rsB*gg.x + bb.x;
            vB[t*2+1] = (vB[t*2+1]-mB)*rsB*gg.y + bb.y;
        }
    }
    __syncthreads();
#pragma unroll
    for (int t = 0; t < 8; t++) {
        sA[(warp*16 + gid)*36     + t*4 + tig] = cvt_f16x2(vA[t*2+1], vA[t*2]);
        sA[(warp*16 + gid + 8)*36 + t*4 + tig] = cvt_f16x2(vB[t*2+1], vB[t*2]);
    }
    CP_WAIT(1);
    __syncthreads();

    uint a2[4][4];
    load_afrag64(a2, sA, warp*16, gid, tig);
    uint hA[16][2];
#pragma unroll
    for (int t = 0; t < 16; t++) {
        float facc[4] = {0,0,0,0};
#pragma unroll
        for (int kk = 0; kk < 4; kk++) {
            uint b0 = sW1[(kk*8 + tig)*132 + t*8 + gid];
            uint b1 = sW1[(kk*8 + 4 + tig)*132 + t*8 + gid];
            mma16n8k16(facc, a2[kk][0], a2[kk][1], a2[kk][2], a2[kk][3], b0, b1);
        }
        float2 bf = *(const float2*)(bf1 + l*FF + t*8 + tig*2);
        float c0 = fmaxf(facc[0] + bf.x, 0.f);
        float c1 = fmaxf(facc[1] + bf.y, 0.f);
        float c2 = fmaxf(facc[2] + bf.x, 0.f);
        float c3 = fmaxf(facc[3] + bf.y, 0.f);
        hA[t][0] = cvt_f16x2(c1, c0);
        hA[t][1] = cvt_f16x2(c3, c2);
    }
    CP_WAIT(0);
    __syncthreads();

#pragma unroll
    for (int t = 0; t < 8; t++) {
        acc[t][0]=0; acc[t][1]=0; acc[t][2]=0; acc[t][3]=0;
#pragma unroll
        for (int kk = 0; kk < 8; kk++) {
            uint b0 = sW2[(kk*8 + tig)*68 + t*8 + gid];
            uint b1 = sW2[(kk*8 + 4 + tig)*68 + t*8 + gid];
            mma16n8k16(acc[t], hA[2*kk][0], hA[2*kk][1], hA[2*kk+1][0], hA[2*kk+1][1], b0, b1);
        }
    }
    {
        float sumA=0, sqA=0, sumB=0, sqB=0;
        float wA[16], wB[16];
#pragma unroll
        for (int t = 0; t < 8; t++) {
            float2 bo2 = *(const float2*)(bf2 + l*D + t*8 + tig*2);
            float a0 = acc[t][0] + bo2.x + vA[t*2];
            float a1 = acc[t][1] + bo2.y + vA[t*2+1];
            float b0 = acc[t][2] + bo2.x + vB[t*2];
            float b1 = acc[t][3] + bo2.y + vB[t*2+1];
            wA[t*2]=a0; wA[t*2+1]=a1; wB[t*2]=b0; wB[t*2+1]=b1;
            sumA += a0+a1; sqA += a0*a0+a1*a1;
            sumB += b0+b1; sqB += b0*b0+b1*b1;
        }
#pragma unroll
        for (int o = 1; o < 4; o <<= 1) {
            sumA += __shfl_xor_sync(0xffffffffu, sumA, o);
            sqA  += __shfl_xor_sync(0xffffffffu, sqA,  o);
            sumB += __shfl_xor_sync(0xffffffffu, sumB, o);
            sqB  += __shfl_xor_sync(0xffffffffu, sqB,  o);
        }
        float mA = sumA*(1.f/64.f), vrA = sqA*(1.f/64.f) - mA*mA;
        float mB = sumB*(1.f/64.f), vrB = sqB*(1.f/64.f) - mB*mB;
        float rsA = rsqrtf(vrA + 1e-5f), rsB = rsqrtf(vrB + 1e-5f);
#pragma unroll
        for (int t = 0; t < 8; t++) {
            float2 gg = *(const float2*)(g2 + l*D + t*8 + tig*2);
            float2 bb = *(const float2*)(b2 + l*D + t*8 + tig*2);
            *(float2*)(g_h + (size_t)rA*D + t*8 + tig*2) =
                make_float2((wA[t*2]-mA)*rsA*gg.x + bb.x, (wA[t*2+1]-mA)*rsA*gg.y + bb.y);
            *(float2*)(g_h + (size_t)rB*D + t*8 + tig*2) =
                make_float2((wB[t*2]-mB)*rsB*gg.x + bb.x, (wB[t*2+1]-mB)*rsB*gg.y + bb.y);
        }
    }
}

// ---------------- 4a) pool partials ----------------
__global__ void k_pool(void) {
    __shared__ float sp2[256];
    int b = blockIdx.x, sc = blockIdx.y, tid = threadIdx.x;
    int col = tid & 63, ch = tid >> 6;
    const float* hb = g_h + (size_t)b*S*D + ((size_t)sc*256 + ch*64)*D;
    float sum = 0.f;
#pragma unroll 8
    for (int s = 0; s < 64; s++) sum += hb[s*D + col];
    sp2[tid] = sum;
    __syncthreads();
    if (tid < 64)
        g_poolp[(b*4 + sc)*D + tid] = sp2[tid] + sp2[tid+64] + sp2[tid+128] + sp2[tid+192];
}

// ---------------- 4b) MLP head + quantum circuit + <Z> + entropy ----------------
#define BARS128() asm volatile("bar.sync 1, 128;" ::: "memory")

__global__ void k_quantum(const float* __restrict__ Wp1, const float* __restrict__ bp1,
                          const float* __restrict__ Wp2, const float* __restrict__ bp2,
                          const float* __restrict__ qw, float* __restrict__ out) {
    __shared__ float sp[64];
    __shared__ float sh[32];
    __shared__ float sang[8];
    __shared__ float2 st[256];
    __shared__ float2 rho[256];
    __shared__ float  sred[256];
    __shared__ float  jc[8], js[8], jpx[8], jpy[8];
    int b = blockIdx.x, tid = threadIdx.x;

    if (tid < 64) {
        const float* pp = g_poolp + b*4*D;
        sp[tid] = (pp[tid] + pp[D+tid] + pp[2*D+tid] + pp[3*D+tid]) * (1.0f/(float)S);
    }
    __syncthreads();
    if (tid < 32) {
        float a = bp1[tid];
#pragma unroll
        for (int i = 0; i < 64; i++) a += sp[i] * Wp1[i*32 + tid];
        sh[tid] = fmaxf(a, 0.f);
    }
    __syncthreads();
    if (tid < 8) {
        float a = bp2[tid];
#pragma unroll
        for (int i = 0; i < 32; i++) a += sh[i] * Wp2[i*8 + tid];
        sang[tid] = tanhf(a) * 3.14159265358979f;
    }

    st[tid] = make_float2(tid == 0 ? 1.f : 0.f, 0.f);
    __syncthreads();

    for (int l = 0; l < QL; l++) {
        for (int w = 0; w < NQ; w++) {
            int mask = 1 << (7 - w);
            float c = cosf(0.5f * sang[w]);
            float s = sinf(0.5f * sang[w]);
            if (!(tid & mask)) {
                float2 v0 = st[tid], v1 = st[tid | mask];
                st[tid]        = make_float2(c*v0.x + s*v1.y,  c*v0.y - s*v1.x);
                st[tid | mask] = make_float2(s*v0.y + c*v1.x, -s*v0.x + c*v1.y);
            }
            __syncthreads();
        }
        for (int w = 0; w < NQ; w++) {
            int mask = 1 << (7 - w);
            float phi = qw[(l*NQ + w)*3 + 0];
            float th  = qw[(l*NQ + w)*3 + 1];
            float om  = qw[(l*NQ + w)*3 + 2];
            float ct = cosf(0.5f*th), stt = sinf(0.5f*th);
            float aa = 0.5f*(phi + om), bb = 0.5f*(phi - om);
            float ca = cosf(aa), sa = sinf(aa), cb = cosf(bb), sb = sinf(bb);
            float2 U00 = make_float2( ct*ca, -ct*sa);
            float2 U01 = make_float2(-stt*cb, -stt*sb);
            float2 U10 = make_float2( stt*cb, -stt*sb);
            float2 U11 = make_float2( ct*ca,  ct*sa);
            if (!(tid & mask)) {
                float2 v0 = st[tid], v1 = st[tid | mask];
                st[tid]        = cadd(cmul(U00, v0), cmul(U01, v1));
                st[tid | mask] = cadd(cmul(U10, v0), cmul(U11, v1));
            }
            __syncthreads();
        }
        for (int w = 0; w < NQ; w++) {
            int mc = 1 << (7 - w);
            int mt = 1 << (7 - ((w + 1) & 7));
            if ((tid & mc) && !(tid & mt)) {
                float2 t0 = st[tid];
                st[tid] = st[tid | mt];
                st[tid | mt] = t0;
            }
            __syncthreads();
        }
    }

    float p = st[tid].x*st[tid].x + st[tid].y*st[tid].y;
    for (int w = 0; w < 3; w++) {
        sred[tid] = (tid & (1 << (7 - w))) ? -p : p;
        __syncthreads();
        for (int off = 128; off > 0; off >>= 1) {
            if (tid < off) sred[tid] += sred[tid + off];
            __syncthreads();
        }
        if (tid == 0) out[b*3 + w] = sred[0];
        __syncthreads();
    }

    {
        int r = tid >> 4, c = tid & 15;
        float2 acc = make_float2(0.f, 0.f);
#pragma unroll
        for (int k = 0; k < 16; k++) {
            float2 mr = st[r*16 + k], mcv = st[c*16 + k];
            acc.x += mr.x*mcv.x + mr.y*mcv.y;
            acc.y += mr.y*mcv.x - mr.x*mcv.y;
        }
        rho[tid] = acc;
    }
    __syncthreads();

    if (tid < 128) {
        int g = tid >> 4, k = tid & 15;
        for (int sweep = 0; sweep < 6; sweep++) {
            for (int rnd = 0; rnd < 15; rnd++) {
                int pa, qa_;
                if (g == 0) { pa = 15; qa_ = rnd; }
                else {
                    pa  = (rnd + g) % 15;
                    qa_ = (rnd + 15 - g) % 15;
                }
                int pp = min(pa, qa_), qq = max(pa, qa_);
                if (k == 0) {
                    float2 apq = rho[pp*16 + qq];
                    float b2v = apq.x*apq.x + apq.y*apq.y;
                    if (b2v > 1e-26f) {
                        float app = rho[pp*16 + pp].x;
                        float aqq = rho[qq*16 + qq].x;
                        float bn  = sqrtf(b2v);
                        float tau = (aqq - app) / (2.f * bn);
                        float rt  = sqrtf(1.f + tau*tau);
                        float t   = (tau >= 0.f) ? 1.f/(tau + rt) : -1.f/(-tau + rt);
                        float cc  = rsqrtf(1.f + t*t);
                        jc[g] = cc; js[g] = t*cc;
                        jpx[g] = apq.x/bn; jpy[g] = apq.y/bn;
                    } else {
                        jc[g] = 1.f; js[g] = 0.f; jpx[g] = 1.f; jpy[g] = 0.f;
                    }
                }
                BARS128();
                float cc = jc[g], ss = js[g];
                float2 ph = make_float2(jpx[g], jpy[g]);
                {
                    float2 rp = rho[pp*16 + k], rq = rho[qq*16 + k];
                    float2 prq  = cmul(ph, rq);
                    float2 cprp = cmulcj(ph, rp);
                    rho[pp*16 + k] = make_float2(cc*rp.x - ss*prq.x,  cc*rp.y - ss*prq.y);
                    rho[qq*16 + k] = make_float2(ss*cprp.x + cc*rq.x, ss*cprp.y + cc*rq.y);
                }
                BARS128();
                {
                    float2 cp = rho[k*16 + pp], cq = rho[k*16 + qq];
                    float2 ccq = cmulcj(ph, cq);
                    float2 pcp = cmul(ph, cp);
                    rho[k*16 + pp] = make_float2(cc*cp.x - ss*ccq.x,  cc*cp.y - ss*ccq.y);
                    rho[k*16 + qq] = make_float2(ss*pcp.x + cc*cq.x, ss*pcp.y + cc*cq.y);
                }
                BARS128();
            }
        }
        if (tid == 0) {
            float ent = 0.f;
#pragma unroll
            for (int kk = 0; kk < 16; kk++) {
                float ev = rho[kk*16 + kk].x;
                ev = fminf(fmaxf(ev, 1e-10f), 1.f);
                ent -= ev * logf(ev);
            }
            out[48 + b] = ent;
        }
    }
}

// ---------------- launch ----------------
extern "C" void kernel_launch(void* const* d_in, const int* in_sizes, int n_in,
                              void* d_out, int out_size) {
    const float* x    = (const float*)d_in[0];
    const float* Wemb = (const float*)d_in[1];
    const float* bemb = (const float*)d_in[2];
    const float* Wq   = (const float*)d_in[3];
    const float* bq   = (const float*)d_in[4];
    const float* Wk   = (const float*)d_in[5];
    const float* bk   = (const float*)d_in[6];
    const float* Wv   = (const float*)d_in[7];
    const float* bv   = (const float*)d_in[8];
    const float* Wo   = (const float*)d_in[9];
    const float* bo   = (const float*)d_in[10];
    const float* ln1g = (const float*)d_in[11];
    const float* ln1b = (const float*)d_in[12];
    const float* ln2g = (const float*)d_in[13];
    const float* ln2b = (const float*)d_in[14];
    const float* Wf1  = (const float*)d_in[15];
    const float* bf1  = (const float*)d_in[16];
    const float* Wf2  = (const float*)d_in[17];
    const float* bf2  = (const float*)d_in[18];
    const float* Wp1  = (const float*)d_in[19];
    const float* bp1  = (const float*)d_in[20];
    const float* Wp2  = (const float*)d_in[21];
    const float* bp2  = (const float*)d_in[22];
    const float* qw   = (const float*)d_in[23];
    float* out = (float*)d_out;

    k_init<<<128 + NL*64, 256>>>(Wq, Wk, Wv, Wo, Wf1, Wf2);
    for (int l = 0; l < NL; l++) {
        dim3 qg(512, 3);
        k_qkv_mma<<<qg, 64>>>(bq, bk, bv, x, Wemb, bemb, l);
        dim3 ag(16, B*H);
        k_attn_mma<<<ag, 128>>>();
        k_block_mma<<<512, 64>>>(bo, ln1g, ln1b, bf1, bf2, ln2g, ln2b, l);
    }
    dim3 pg(B, 4);
    k_pool<<<pg, 256>>>();
    k_quantum<<<B, 256>>>(Wp1, bp1, Wp2, bp2, qw, out);
}

// round 16
// speedup vs baseline: 1.0224x; 1.0224x over previous
#include <cuda_runtime.h>
#include <cuda_fp16.h>
#include <math.h>

#define B   16
#define S   1024
#define NF  5
#define D   64
#define H   8
#define HD  8
#define NL  2
#define FF  128
#define NQ  8
#define QL  3
#define BS  (B*S)
#define CK2  512
#define VPAD2 520

typedef unsigned long long ull;
typedef unsigned int uint;

// ---------------- device scratch ----------------
__device__ float g_h  [BS*D];
// head-major fp16 q/k/v: [b][h][s][4 uints]  (k pre-scaled by scale*log2e)
__device__ uint  g_q16[BS*32];
__device__ uint  g_k16[BS*32];
__device__ uint  g_v16[BS*32];
__device__ float g_pe [S*D];
__device__ uint  g_parth[(size_t)2*128*S*6];   // fp16 partials (4 half2 + lsum f32 + pad)
__device__ float g_poolp[B*4*D];
// prepacked half2 weights (B-fragment layout)
__device__ uint g_pWq[NL*32*68];
__device__ uint g_pWk[NL*32*68];
__device__ uint g_pWv[NL*32*68];
__device__ uint g_pWo[NL*32*68];
__device__ uint g_pW1[NL*32*132];
__device__ uint g_pW2[NL*64*68];

// ---------------- mma / f16 / async helpers ----------------
__device__ __forceinline__ void mma16n8k8_f16(uint& d0, uint& d1, uint a0, uint a1, uint b0) {
    asm volatile("mma.sync.aligned.m16n8k8.row.col.f16.f16.f16.f16 "
        "{%0,%1}, {%2,%3}, {%4}, {%5,%6};"
        : "=r"(d0), "=r"(d1)
        : "r"(a0), "r"(a1), "r"(b0), "r"(0u), "r"(0u));
}
__device__ __forceinline__ void mma16n8k16(float* d,
                                           uint a0, uint a1, uint a2, uint a3,
                                           uint b0, uint b1) {
    asm volatile("mma.sync.aligned.m16n8k16.row.col.f32.f16.f16.f32 "
        "{%0,%1,%2,%3}, {%4,%5,%6,%7}, {%8,%9}, {%0,%1,%2,%3};"
        : "+f"(d[0]), "+f"(d[1]), "+f"(d[2]), "+f"(d[3])
        : "r"(a0), "r"(a1), "r"(a2), "r"(a3), "r"(b0), "r"(b1));
}
__device__ __forceinline__ uint cvt_f16x2(float hi, float lo) {
    uint r; asm("cvt.rn.f16x2.f32 %0, %1, %2;" : "=r"(r) : "f"(hi), "f"(lo)); return r;
}
__device__ __forceinline__ uint hex2x2(uint x) {
    uint r; asm("ex2.approx.f16x2 %0, %1;" : "=r"(r) : "r"(x)); return r;
}
__device__ __forceinline__ void cpasync16(uint smem_addr, const void* gptr) {
    asm volatile("cp.async.cg.shared.global [%0], [%1], 16;" :: "r"(smem_addr), "l"(gptr));
}
#define CP_COMMIT()  asm volatile("cp.async.commit_group;" ::: "memory")
#define CP_WAIT(n)   asm volatile("cp.async.wait_group %0;" :: "n"(n) : "memory")
__device__ __forceinline__ uint smem_u32p(const void* p) {
    return (uint)__cvta_generic_to_shared(p);
}

// ---------------- complex helpers ----------------
__device__ __forceinline__ float2 cmul(float2 a, float2 b) {
    return make_float2(a.x*b.x - a.y*b.y, a.x*b.y + a.y*b.x);
}
__device__ __forceinline__ float2 cmulcj(float2 a, float2 b) {
    return make_float2(a.x*b.x + a.y*b.y, a.x*b.y - a.y*b.x);
}
__device__ __forceinline__ float2 cadd(float2 a, float2 b) {
    return make_float2(a.x + b.x, a.y + b.y);
}

// ---------------- 0) init: pe table + weight prepack ----------------
__global__ void k_init(const float* __restrict__ Wq, const float* __restrict__ Wk,
                       const float* __restrict__ Wv, const float* __restrict__ Wo,
                       const float* __restrict__ Wf1, const float* __restrict__ Wf2) {
    int bidx = blockIdx.x;
    int tid = threadIdx.x;
    if (bidx < 128) {
        int idx = bidx * 256 + tid;
        int s = idx >> 5, p = idx & 31;
        float div = __expf(-0.14391156831212787f * (float)(2*p));
        float sn, cs;
        sincosf((float)s * div, &sn, &cs);
        g_pe[s*64 + 2*p]     = sn;
        g_pe[s*64 + 2*p + 1] = cs;
    } else {
        int idx = (bidx - 128) * 256 + tid;    // < NL*16384
        int l = idx / 16384;
        int r = idx % 16384;
        if (r < 8192) {
            int m = r >> 11;
            int q = r & 2047;
            int ip = q >> 6, n = q & 63;
            const float* W = (m == 0) ? (Wq + l*4096) : (m == 1) ? (Wk + l*4096)
                           : (m == 2) ? (Wv + l*4096) : (Wo + l*4096);
            uint* dst = (m == 0) ? g_pWq : (m == 1) ? g_pWk : (m == 2) ? g_pWv : g_pWo;
            dst[l*2176 + ip*68 + n] = cvt_f16x2(W[(2*ip+1)*64 + n], W[(2*ip)*64 + n]);
        } else if (r < 12288) {
            int q = r - 8192;
            int ip = q >> 7, n = q & 127;
            const float* W = Wf1 + l*8192;
            g_pW1[l*4224 + ip*132 + n] = cvt_f16x2(W[(2*ip+1)*128 + n], W[(2*ip)*128 + n]);
        } else {
            int q = r - 12288;
            int ip = q >> 6, n = q & 63;
            const float* W = Wf2 + l*8192;
            g_pW2[l*4352 + ip*68 + n] = cvt_f16x2(W[(2*ip+1)*64 + n], W[(2*ip)*64 + n]);
        }
    }
}

// ======== MMA GEMM common fragment loaders ========
__device__ __forceinline__ void load_afrag64(uint (&a)[4][4], const uint* sA, int rbase, int gid, int tig) {
    const uint* r0 = sA + (rbase + gid)*36;
    const uint* r1 = sA + (rbase + gid + 8)*36;
#pragma unroll
    for (int kk = 0; kk < 4; kk++) {
        a[kk][0] = r0[kk*8 + tig];
        a[kk][1] = r1[kk*8 + tig];
        a[kk][2] = r0[kk*8 + 4 + tig];
        a[kk][3] = r1[kk*8 + 4 + tig];
    }
}

// ---------------- 1) QKV projection: cp.async weights, head-major fp16 outputs ----------------
__global__ void __launch_bounds__(64) k_qkv_mma(
        const float* __restrict__ bq, const float* __restrict__ bk,
        const float* __restrict__ bv,
        const float* __restrict__ x,  const float* __restrict__ Wemb,
        const float* __restrict__ bemb, int l) {
    __shared__ uint  sA [32*36];
    __shared__ uint  sW [2176];
    __shared__ float sX [32*NF];
    int tid = threadIdx.x;
    int row0 = blockIdx.x * 32;
    int m = blockIdx.y;
    const uint* pW    = ((m == 0) ? g_pWq : (m == 1) ? g_pWk : g_pWv) + l*2176;
    const float* bias = ((m == 0) ? bq : (m == 1) ? bk : bv) + l*D;
    uint* out         = (m == 0) ? g_q16 : (m == 1) ? g_k16 : g_v16;
    const float pre   = 0.35355339059327373f * 1.4426950408889634f;
    const float oscale = (m == 1) ? pre : 1.0f;   // pre-scale K

    {
        uint sw = smem_u32p(sW);
        for (int i = tid; i < 544; i += 64)
            cpasync16(sw + i*16, pW + i*4);
        CP_COMMIT();
    }

    if (l == 0) {
        for (int idx = tid; idx < 32*NF; idx += 64)
            sX[idx] = x[(size_t)(row0 + idx/NF)*NF + idx%NF];
        __syncthreads();
        for (int idx = tid; idx < 1024; idx += 64) {
            int r = idx >> 5, c2 = idx & 31;
            int row = row0 + r;
            int s = row & (S-1);
            int c = c2*2;
            float v0 = bemb[c]   + g_pe[s*64 + c];
            float v1 = bemb[c+1] + g_pe[s*64 + c + 1];
            const float* xr = sX + r*NF;
#pragma unroll
            for (int f = 0; f < NF; f++) {
                v0 += xr[f] * Wemb[f*D + c];
                v1 += xr[f] * Wemb[f*D + c + 1];
            }
            sA[r*36 + c2] = cvt_f16x2(v1, v0);
            if (m == 0) *(float2*)(g_h + (size_t)row*D + c) = make_float2(v0, v1);
        }
    } else {
        for (int idx = tid; idx < 1024; idx += 64) {
            int r = idx >> 5, c2 = idx & 31;
            float2 v = *(const float2*)(g_h + (size_t)(row0 + r)*D + c2*2);
            sA[r*36 + c2] = cvt_f16x2(v.y, v.x);
        }
    }
    CP_WAIT(0);
    __syncthreads();

    int warp = tid >> 5, lane = tid & 31;
    int gid = lane >> 2, tig = lane & 3;
    uint a[4][4];
    load_afrag64(a, sA, warp*16, gid, tig);

#pragma unroll
    for (int t = 0; t < 8; t++) {
        float acc[4] = {0,0,0,0};
#pragma unroll
        for (int kk = 0; kk < 4; kk++) {
            uint b0 = sW[(kk*8 + tig)*68 + t*8 + gid];
            uint b1 = sW[(kk*8 + 4 + tig)*68 + t*8 + gid];
            mma16n8k16(acc, a[kk][0], a[kk][1], a[kk][2], a[kk][3], b0, b1);
        }
        float2 bv2 = *(const float2*)(bias + t*8 + tig*2);
        int r = row0 + warp*16 + gid;
        // head-major store: [b][h=t][s][4]; rows r and r+8 (same batch: 32-row tile)
        int bb = r >> 10, s = r & (S-1);
        size_t obase = ((size_t)(bb*8 + t)*S + s)*4 + tig;
        out[obase] =
            cvt_f16x2((acc[1] + bv2.y) * oscale, (acc[0] + bv2.x) * oscale);
        out[obase + 8*4] =
            cvt_f16x2((acc[3] + bv2.y) * oscale, (acc[2] + bv2.x) * oscale);
    }
}

// ---------------- 2) split-K attention: head-major fp16, E/O chains, fp16 partials ----------------
__global__ void __launch_bounds__(128) k_attn_mma() {
    __shared__ uint   sK [CK2*4];     // half2 units, [key][4]
    __shared__ __half sVT[8*VPAD2];
    int tid = threadIdx.x;
    int bh  = blockIdx.y;
    int b   = bh >> 3;
    int qt  = blockIdx.x >> 1;
    int ck  = blockIdx.x & 1;
    int k0  = ck * CK2;
    const uint* kbase = g_k16 + ((size_t)bh*S + k0)*4;
    const uint* vbase = g_v16 + ((size_t)bh*S + k0)*4;
    // K: straight coalesced copy
    for (int i = tid; i < CK2*4; i += 128)
        sK[i] = kbase[i];
    // V: coalesced uint loads + in-smem transpose
    for (int i = tid; i < CK2*4; i += 128) {
        int key = i >> 2, u = i & 3;
        uint w = vbase[i];
        __half2 hv = *(__half2*)&w;
        sVT[(2*u)*VPAD2 + key]   = __low2half(hv);
        sVT[(2*u+1)*VPAD2 + key] = __high2half(hv);
    }
    __syncthreads();

    int warp = tid >> 5, lane = tid & 31;
    int gid  = lane >> 2, tig = lane & 3;
    int q0   = qt * 128 + warp * 32;

    uint qa[2][2];
#pragma unroll
    for (int t2 = 0; t2 < 2; t2++) {
#pragma unroll
        for (int hf = 0; hf < 2; hf++) {
            int qrow = q0 + t2*16 + gid + hf*8;
            qa[t2][hf] = g_q16[((size_t)bh*S + qrow)*4 + tig];
        }
    }

    float acc0E[4] = {0,0,0,0}, acc0O[4] = {0,0,0,0};
    float acc1E[4] = {0,0,0,0}, acc1O[4] = {0,0,0,0};
    float lac0E[4] = {0,0,0,0}, lac0O[4] = {0,0,0,0};
    float lac1E[4] = {0,0,0,0}, lac1O[4] = {0,0,0,0};
    const uint ones2 = 0x3C003C00u;
    const uint*   kptr = sK + gid*4 + tig;
    const __half* vptr = sVT + gid*VPAD2 + tig*2;

    for (int j0 = 0; j0 < CK2; j0 += 32) {
        uint kb0 = kptr[j0*4];
        uint kb1 = kptr[j0*4 + 32];
        uint kb2 = kptr[j0*4 + 64];
        uint kb3 = kptr[j0*4 + 96];
        uint vb0 = *(const uint*)(vptr + j0);
        uint vb1 = *(const uint*)(vptr + j0 + 8);
        uint vb2 = *(const uint*)(vptr + j0 + 16);
        uint vb3 = *(const uint*)(vptr + j0 + 24);
        {
            uint s01a, s23a, s01b, s23b;
            mma16n8k8_f16(s01a, s23a, qa[0][0], qa[0][1], kb0);
            mma16n8k8_f16(s01b, s23b, qa[0][0], qa[0][1], kb1);
            uint p0 = hex2x2(s01a), p1 = hex2x2(s23a);
            uint p2 = hex2x2(s01b), p3 = hex2x2(s23b);
            mma16n8k16(acc0E, p0, p1, p2, p3, vb0, vb1);
            mma16n8k16(lac0E, p0, p1, p2, p3, ones2, ones2);
        }
        {
            uint s01a, s23a, s01b, s23b;
            mma16n8k8_f16(s01a, s23a, qa[1][0], qa[1][1], kb0);
            mma16n8k8_f16(s01b, s23b, qa[1][0], qa[1][1], kb1);
            uint p0 = hex2x2(s01a), p1 = hex2x2(s23a);
            uint p2 = hex2x2(s01b), p3 = hex2x2(s23b);
            mma16n8k16(acc1E, p0, p1, p2, p3, vb0, vb1);
            mma16n8k16(lac1E, p0, p1, p2, p3, ones2, ones2);
        }
        {
            uint s01a, s23a, s01b, s23b;
            mma16n8k8_f16(s01a, s23a, qa[0][0], qa[0][1], kb2);
            mma16n8k8_f16(s01b, s23b, qa[0][0], qa[0][1], kb3);
            uint p0 = hex2x2(s01a), p1 = hex2x2(s23a);
            uint p2 = hex2x2(s01b), p3 = hex2x2(s23b);
            mma16n8k16(acc0O, p0, p1, p2, p3, vb2, vb3);
            mma16n8k16(lac0O, p0, p1, p2, p3, ones2, ones2);
        }
        {
            uint s01a, s23a, s01b, s23b;
            mma16n8k8_f16(s01a, s23a, qa[1][0], qa[1][1], kb2);
            mma16n8k8_f16(s01b, s23b, qa[1][0], qa[1][1], kb3);
            uint p0 = hex2x2(s01a), p1 = hex2x2(s23a);
            uint p2 = hex2x2(s01b), p3 = hex2x2(s23b);
            mma16n8k16(acc1O, p0, p1, p2, p3, vb2, vb3);
            mma16n8k16(lac1O, p0, p1, p2, p3, ones2, ones2);
        }
    }

    // merge + pack fp16; layout [ck][bh][q][6 uints]
    size_t base = ((size_t)ck*128 + bh)*S;
    {
        uint* pp = g_parth + (base + q0 + gid)*6;
        pp[tig] = cvt_f16x2(acc0E[1] + acc0O[1], acc0E[0] + acc0O[0]);
        if (tig == 0) pp[4] = __float_as_uint(lac0E[0] + lac0O[0]);
        pp = g_parth + (base + q0 + gid + 8)*6;
        pp[tig] = cvt_f16x2(acc0E[3] + acc0O[3], acc0E[2] + acc0O[2]);
        if (tig == 0) pp[4] = __float_as_uint(lac0E[2] + lac0O[2]);
        pp = g_parth + (base + q0 + 16 + gid)*6;
        pp[tig] = cvt_f16x2(acc1E[1] + acc1O[1], acc1E[0] + acc1O[0]);
        if (tig == 0) pp[4] = __float_as_uint(lac1E[0] + lac1O[0]);
        pp = g_parth + (base + q0 + 24 + gid)*6;
        pp[tig] = cvt_f16x2(acc1E[3] + acc1O[3], acc1E[2] + acc1O[2]);
        if (tig == 0) pp[4] = __float_as_uint(lac1E[2] + lac1O[2]);
    }
}

// ---------------- 3) FUSED block: cp.async-staged weights, fp16 partial combine ----------------
__global__ void __launch_bounds__(64) k_block_mma(
        const float* __restrict__ bo,
        const float* __restrict__ g1, const float* __restrict__ b1,
        const float* __restrict__ bf1, const float* __restrict__ bf2,
        const float* __restrict__ g2, const float* __restrict__ b2, int l) {
    __shared__ uint sA [32*36];
    __shared__ uint sWo[2176];
    __shared__ uint sW1[4224];
    __shared__ uint sW2[4352];
    int tid = threadIdx.x;
    int row0 = blockIdx.x * 32;

    {
        const uint* pWo = g_pWo + l*2176;
        const uint* pW1 = g_pW1 + l*4224;
        const uint* pW2 = g_pW2 + l*4352;
        uint so = smem_u32p(sWo), s1 = smem_u32p(sW1), s2 = smem_u32p(sW2);
        for (int i = tid; i < 544; i += 64)  cpasync16(so + i*16, pWo + i*4);
        CP_COMMIT();
        for (int i = tid; i < 1056; i += 64) cpasync16(s1 + i*16, pW1 + i*4);
        CP_COMMIT();
        for (int i = tid; i < 1088; i += 64) cpasync16(s2 + i*16, pW2 + i*4);
        CP_COMMIT();
    }

    for (int idx = tid; idx < 1024; idx += 64) {
        int r = idx >> 5, c2 = idx & 31;
        int grow = row0 + r;
        int q  = grow & (S-1);
        int bb = grow >> 10;
        int hh = c2 >> 2;
        int bh = bb*8 + hh;
        int pi = c2 & 3;
        const uint* p0 = g_parth + ((size_t)(0*128 + bh)*S + q)*6;
        const uint* p1 = g_parth + ((size_t)(1*128 + bh)*S + q)*6;
        float2 a0 = __half22float2(*(const __half2*)&p0[pi]);
        float2 a1 = __half22float2(*(const __half2*)&p1[pi]);
        float inv = 1.0f / (__uint_as_float(p0[4]) + __uint_as_float(p1[4]));
        sA[r*36 + c2] = cvt_f16x2((a0.y + a1.y) * inv, (a0.x + a1.x) * inv);
    }
    CP_WAIT(2);
    __syncthreads();

    int warp = tid >> 5, lane = tid & 31;
    int gid = lane >> 2, tig = lane & 3;
    int rA = row0 + warp*16 + gid;
    int rB = rA + 8;

    uint a[4][4];
    load_afrag64(a, sA, warp*16, gid, tig);
    float acc[8][4];
#pragma unroll
    for (int t = 0; t < 8; t++) {
        acc[t][0]=0; acc[t][1]=0; acc[t][2]=0; acc[t][3]=0;
#pragma unroll
        for (int kk = 0; kk < 4; kk++) {
            uint b0 = sWo[(kk*8 + tig)*68 + t*8 + gid];
            uint b1 = sWo[(kk*8 + 4 + tig)*68 + t*8 + gid];
            mma16n8k16(acc[t], a[kk][0], a[kk][1], a[kk][2], a[kk][3], b0, b1);
        }
    }
    float vA[16], vB[16];
    {
        float sumA=0, sqA=0, sumB=0, sqB=0;
#pragma unroll
        for (int t = 0; t < 8; t++) {
            float2 bo2 = *(const float2*)(bo + l*D + t*8 + tig*2);
            float2 hA = *(const float2*)(g_h + (size_t)rA*D + t*8 + tig*2);
            float2 hB = *(const float2*)(g_h + (size_t)rB*D + t*8 + tig*2);
            float a0 = acc[t][0] + bo2.x + hA.x;
            float a1 = acc[t][1] + bo2.y + hA.y;
            float b0 = acc[t][2] + bo2.x + hB.x;
            float b1 = acc[t][3] + bo2.y + hB.y;
            vA[t*2]=a0; vA[t*2+1]=a1; vB[t*2]=b0; vB[t*2+1]=b1;
            sumA += a0+a1; sqA += a0*a0+a1*a1;
            sumB += b0+b1; sqB += b0*b0+b1*b1;
        }
#pragma unroll
        for (int o = 1; o < 4; o <<= 1) {
            sumA += __shfl_xor_sync(0xffffffffu, sumA, o);
            sqA  += __shfl_xor_sync(0xffffffffu, sqA,  o);
            sumB += __shfl_xor_sync(0xffffffffu, sumB, o);
            sqB  += __shfl_xor_sync(0xffffffffu, sqB,  o);
        }
        float mA = sumA*(1.f/64.f), vrA = sqA*(1.f/64.f) - mA*mA;
        float mB = sumB*(1.f/64.f), vrB = sqB*(1.f/64.f) - mB*mB;
        float rsA = rsqrtf(vrA + 1e-5f), rsB = rsqrtf(vrB + 1e-5f);
#pragma unroll
        for (int t = 0; t < 8; t++) {
            float2 gg = *(const float2*)(g1 + l*D + t*8 + tig*2);
            float2 bb = *(const float2*)(b1 + l*D + t*8 + tig*2);
            vA[t*2]   = (vA[t*2]  -mA)*rsA*gg.x + bb.x;
            vA[t*2+1] = (vA[t*2+1]-mA)*rsA*gg.y + bb.y;
            vB[t*2]   = (vB[t*2]  -mB)*rsB*gg.x + bb.x;
            vB[t*2+1] = (vB[t*2+1]-mB)*rsB*gg.y + bb.y;
        }
    }
    __syncthreads();
#pragma unroll
    for (int t = 0; t < 8; t++) {
        sA[(warp*16 + gid)*36     + t*4 + tig] = cvt_f16x2(vA[t*2+1], vA[t*2]);
        sA[(warp*16 + gid + 8)*36 + t*4 + tig] = cvt_f16x2(vB[t*2+1], vB[t*2]);
    }
    CP_WAIT(1);
    __syncthreads();

    uint a2[4][4];
    load_afrag64(a2, sA, warp*16, gid, tig);
    uint hA[16][2];
#pragma unroll
    for (int t = 0; t < 16; t++) {
        float facc[4] = {0,0,0,0};
#pragma unroll
        for (int kk = 0; kk < 4; kk++) {
            uint b0 = sW1[(kk*8 + tig)*132 + t*8 + gid];
            uint b1 = sW1[(kk*8 + 4 + tig)*132 + t*8 + gid];
            mma16n8k16(facc, a2[kk][0], a2[kk][1], a2[kk][2], a2[kk][3], b0, b1);
        }
        float2 bf = *(const float2*)(bf1 + l*FF + t*8 + tig*2);
        float c0 = fmaxf(facc[0] + bf.x, 0.f);
        float c1 = fmaxf(facc[1] + bf.y, 0.f);
        float c2 = fmaxf(facc[2] + bf.x, 0.f);
        float c3 = fmaxf(facc[3] + bf.y, 0.f);
        hA[t][0] = cvt_f16x2(c1, c0);
        hA[t][1] = cvt_f16x2(c3, c2);
    }
    CP_WAIT(0);
    __syncthreads();

#pragma unroll
    for (int t = 0; t < 8; t++) {
        acc[t][0]=0; acc[t][1]=0; acc[t][2]=0; acc[t][3]=0;
#pragma unroll
        for (int kk = 0; kk < 8; kk++) {
            uint b0 = sW2[(kk*8 + tig)*68 + t*8 + gid];
            uint b1 = sW2[(kk*8 + 4 + tig)*68 + t*8 + gid];
            mma16n8k16(acc[t], hA[2*kk][0], hA[2*kk][1], hA[2*kk+1][0], hA[2*kk+1][1], b0, b1);
        }
    }
    {
        float sumA=0, sqA=0, sumB=0, sqB=0;
        float wA[16], wB[16];
#pragma unroll
        for (int t = 0; t < 8; t++) {
            float2 bo2 = *(const float2*)(bf2 + l*D + t*8 + tig*2);
            float a0 = acc[t][0] + bo2.x + vA[t*2];
            float a1 = acc[t][1] + bo2.y + vA[t*2+1];
            float b0 = acc[t][2] + bo2.x + vB[t*2];
            float b1 = acc[t][3] + bo2.y + vB[t*2+1];
            wA[t*2]=a0; wA[t*2+1]=a1; wB[t*2]=b0; wB[t*2+1]=b1;
            sumA += a0+a1; sqA += a0*a0+a1*a1;
            sumB += b0+b1; sqB += b0*b0+b1*b1;
        }
#pragma unroll
        for (int o = 1; o < 4; o <<= 1) {
            sumA += __shfl_xor_sync(0xffffffffu, sumA, o);
            sqA  += __shfl_xor_sync(0xffffffffu, sqA,  o);
            sumB += __shfl_xor_sync(0xffffffffu, sumB, o);
            sqB  += __shfl_xor_sync(0xffffffffu, sqB,  o);
        }
        float mA = sumA*(1.f/64.f), vrA = sqA*(1.f/64.f) - mA*mA;
        float mB = sumB*(1.f/64.f), vrB = sqB*(1.f/64.f) - mB*mB;
        float rsA = rsqrtf(vrA + 1e-5f), rsB = rsqrtf(vrB + 1e-5f);
#pragma unroll
        for (int t = 0; t < 8; t++) {
            float2 gg = *(const float2*)(g2 + l*D + t*8 + tig*2);
            float2 bb = *(const float2*)(b2 + l*D + t*8 + tig*2);
            *(float2*)(g_h + (size_t)rA*D + t*8 + tig*2) =
                make_float2((wA[t*2]-mA)*rsA*gg.x + bb.x, (wA[t*2+1]-mA)*rsA*gg.y + bb.y);
            *(float2*)(g_h + (size_t)rB*D + t*8 + tig*2) =
                make_float2((wB[t*2]-mB)*rsB*gg.x + bb.x, (wB[t*2+1]-mB)*rsB*gg.y + bb.y);
        }
    }
}

// ---------------- 4a) pool partials ----------------
__global__ void k_pool(void) {
    __shared__ float sp2[256];
    int b = blockIdx.x, sc = blockIdx.y, tid = threadIdx.x;
    int col = tid & 63, ch = tid >> 6;
    const float* hb = g_h + (size_t)b*S*D + ((size_t)sc*256 + ch*64)*D;
    float sum = 0.f;
#pragma unroll 8
    for (int s = 0; s < 64; s++) sum += hb[s*D + col];
    sp2[tid] = sum;
    __syncthreads();
    if (tid < 64)
        g_poolp[(b*4 + sc)*D + tid] = sp2[tid] + sp2[tid+64] + sp2[tid+128] + sp2[tid+192];
}

// ---------------- 4b) MLP head + quantum circuit + <Z> + entropy ----------------
#define BARS128() asm volatile("bar.sync 1, 128;" ::: "memory")

__global__ void k_quantum(const float* __restrict__ Wp1, const float* __restrict__ bp1,
                          const float* __restrict__ Wp2, const float* __restrict__ bp2,
                          const float* __restrict__ qw, float* __restrict__ out) {
    __shared__ float sp[64];
    __shared__ float sh[32];
    __shared__ float sang[8];
    __shared__ float2 st[256];
    __shared__ float2 rho[256];
    __shared__ float  sred[256];
    __shared__ float  jc[8], js[8], jpx[8], jpy[8];
    int b = blockIdx.x, tid = threadIdx.x;

    if (tid < 64) {
        const float* pp = g_poolp + b*4*D;
        sp[tid] = (pp[tid] + pp[D+tid] + pp[2*D+tid] + pp[3*D+tid]) * (1.0f/(float)S);
    }
    __syncthreads();
    if (tid < 32) {
        float a = bp1[tid];
#pragma unroll
        for (int i = 0; i < 64; i++) a += sp[i] * Wp1[i*32 + tid];
        sh[tid] = fmaxf(a, 0.f);
    }
    __syncthreads();
    if (tid < 8) {
        float a = bp2[tid];
#pragma unroll
        for (int i = 0; i < 32; i++) a += sh[i] * Wp2[i*8 + tid];
        sang[tid] = tanhf(a) * 3.14159265358979f;
    }

    st[tid] = make_float2(tid == 0 ? 1.f : 0.f, 0.f);
    __syncthreads();

    for (int l = 0; l < QL; l++) {
        for (int w = 0; w < NQ; w++) {
            int mask = 1 << (7 - w);
            float c = cosf(0.5f * sang[w]);
            float s = sinf(0.5f * sang[w]);
            if (!(tid & mask)) {
                float2 v0 = st[tid], v1 = st[tid | mask];
                st[tid]        = make_float2(c*v0.x + s*v1.y,  c*v0.y - s*v1.x);
                st[tid | mask] = make_float2(s*v0.y + c*v1.x, -s*v0.x + c*v1.y);
            }
            __syncthreads();
        }
        for (int w = 0; w < NQ; w++) {
            int mask = 1 << (7 - w);
            float phi = qw[(l*NQ + w)*3 + 0];
            float th  = qw[(l*NQ + w)*3 + 1];
            float om  = qw[(l*NQ + w)*3 + 2];
            float ct = cosf(0.5f*th), stt = sinf(0.5f*th);
            float aa = 0.5f*(phi + om), bb = 0.5f*(phi - om);
            float ca = cosf(aa), sa = sinf(aa), cb = cosf(bb), sb = sinf(bb);
            float2 U00 = make_float2( ct*ca, -ct*sa);
            float2 U01 = make_float2(-stt*cb, -stt*sb);
            float2 U10 = make_float2( stt*cb, -stt*sb);
            float2 U11 = make_float2( ct*ca,  ct*sa);
            if (!(tid & mask)) {
                float2 v0 = st[tid], v1 = st[tid | mask];
                st[tid]        = cadd(cmul(U00, v0), cmul(U01, v1));
                st[tid | mask] = cadd(cmul(U10, v0), cmul(U11, v1));
            }
            __syncthreads();
        }
        for (int w = 0; w < NQ; w++) {
            int mc = 1 << (7 - w);
            int mt = 1 << (7 - ((w + 1) & 7));
            if ((tid & mc) && !(tid & mt)) {
                float2 t0 = st[tid];
                st[tid] = st[tid | mt];
                st[tid | mt] = t0;
            }
            __syncthreads();
        }
    }

    float p = st[tid].x*st[tid].x + st[tid].y*st[tid].y;
    for (int w = 0; w < 3; w++) {
        sred[tid] = (tid & (1 << (7 - w))) ? -p : p;
        __syncthreads();
        for (int off = 128; off > 0; off >>= 1) {
            if (tid < off) sred[tid] += sred[tid + off];
            __syncthreads();
        }
        if (tid == 0) out[b*3 + w] = sred[0];
        __syncthreads();
    }

    {
        int r = tid >> 4, c = tid & 15;
        float2 acc = make_float2(0.f, 0.f);
#pragma unroll
        for (int k = 0; k < 16; k++) {
            float2 mr = st[r*16 + k], mcv = st[c*16 + k];
            acc.x += mr.x*mcv.x + mr.y*mcv.y;
            acc.y += mr.y*mcv.x - mr.x*mcv.y;
        }
        rho[tid] = acc;
    }
    __syncthreads();

    if (tid < 128) {
        int g = tid >> 4, k = tid & 15;
        for (int sweep = 0; sweep < 6; sweep++) {
            for (int rnd = 0; rnd < 15; rnd++) {
                int pa, qa_;
                if (g == 0) { pa = 15; qa_ = rnd; }
                else {
                    pa  = (rnd + g) % 15;
                    qa_ = (rnd + 15 - g) % 15;
                }
                int pp = min(pa, qa_), qq = max(pa, qa_);
                if (k == 0) {
                    float2 apq = rho[pp*16 + qq];
                    float b2v = apq.x*apq.x + apq.y*apq.y;
                    if (b2v > 1e-26f) {
                        float app = rho[pp*16 + pp].x;
                        float aqq = rho[qq*16 + qq].x;
                        float bn  = sqrtf(b2v);
                        float tau = (aqq - app) / (2.f * bn);
                        float rt  = sqrtf(1.f + tau*tau);
                        float t   = (tau >= 0.f) ? 1.f/(tau + rt) : -1.f/(-tau + rt);
                        float cc  = rsqrtf(1.f + t*t);
                        jc[g] = cc; js[g] = t*cc;
                        jpx[g] = apq.x/bn; jpy[g] = apq.y/bn;
                    } else {
                        jc[g] = 1.f; js[g] = 0.f; jpx[g] = 1.f; jpy[g] = 0.f;
                    }
                }
                BARS128();
                float cc = jc[g], ss = js[g];
                float2 ph = make_float2(jpx[g], jpy[g]);
                {
                    float2 rp = rho[pp*16 + k], rq = rho[qq*16 + k];
                    float2 prq  = cmul(ph, rq);
                    float2 cprp = cmulcj(ph, rp);
                    rho[pp*16 + k] = make_float2(cc*rp.x - ss*prq.x,  cc*rp.y - ss*prq.y);
                    rho[qq*16 + k] = make_float2(ss*cprp.x + cc*rq.x, ss*cprp.y + cc*rq.y);
                }
                BARS128();
                {
                    float2 cp = rho[k*16 + pp], cq = rho[k*16 + qq];
                    float2 ccq = cmulcj(ph, cq);
                    float2 pcp = cmul(ph, cp);
                    rho[k*16 + pp] = make_float2(cc*cp.x - ss*ccq.x,  cc*cp.y - ss*ccq.y);
                    rho[k*16 + qq] = make_float2(ss*pcp.x + cc*cq.x, ss*pcp.y + cc*cq.y);
                }
                BARS128();
            }
        }
        if (tid == 0) {
            float ent = 0.f;
#pragma unroll
            for (int kk = 0; kk < 16; kk++) {
                float ev = rho[kk*16 + kk].x;
                ev = fminf(fmaxf(ev, 1e-10f), 1.f);
                ent -= ev * logf(ev);
            }
            out[48 + b] = ent;
        }
    }
}

// ---------------- launch ----------------
extern "C" void kernel_launch(void* const* d_in, const int* in_sizes, int n_in,
                              void* d_out, int out_size) {
    const float* x    = (const float*)d_in[0];
    const float* Wemb = (const float*)d_in[1];
    const float* bemb = (const float*)d_in[2];
    const float* Wq   = (const float*)d_in[3];
    const float* bq   = (const float*)d_in[4];
    const float* Wk   = (const float*)d_in[5];
    const float* bk   = (const float*)d_in[6];
    const float* Wv   = (const float*)d_in[7];
    const float* bv   = (const float*)d_in[8];
    const float* Wo   = (const float*)d_in[9];
    const float* bo   = (const float*)d_in[10];
    const float* ln1g = (const float*)d_in[11];
    const float* ln1b = (const float*)d_in[12];
    const float* ln2g = (const float*)d_in[13];
    const float* ln2b = (const float*)d_in[14];
    const float* Wf1  = (const float*)d_in[15];
    const float* bf1  = (const float*)d_in[16];
    const float* Wf2  = (const float*)d_in[17];
    const float* bf2  = (const float*)d_in[18];
    const float* Wp1  = (const float*)d_in[19];
    const float* bp1  = (const float*)d_in[20];
    const float* Wp2  = (const float*)d_in[21];
    const float* bp2  = (const float*)d_in[22];
    const float* qw   = (const float*)d_in[23];
    float* out = (float*)d_out;

    k_init<<<128 + NL*64, 256>>>(Wq, Wk, Wv, Wo, Wf1, Wf2);
    for (int l = 0; l < NL; l++) {
        dim3 qg(512, 3);
        k_qkv_mma<<<qg, 64>>>(bq, bk, bv, x, Wemb, bemb, l);
        dim3 ag(16, B*H);
        k_attn_mma<<<ag, 128>>>();
        k_block_mma<<<512, 64>>>(bo, ln1g, ln1b, bf1, bf2, ln2g, ln2b, l);
    }
    dim3 pg(B, 4);
    k_pool<<<pg, 256>>>();
    k_quantum<<<B, 256>>>(Wp1, bp1, Wp2, bp2, qw, out);
}